// round 7
// baseline (speedup 1.0000x reference)
#include <cuda_runtime.h>
#include <cuda_fp16.h>
#include <stdint.h>

#define VOCAB 100000
#define EMBED 64
#define KIDS  20
#define BROWS (1024 * 50)          // B*S output rows

// Wt in fp16, [V, E]: each vocab row = 64 halves = 128 B = ONE L2 line.
// 12.8 MB — L2-resident (126 MB L2).
__device__ __half g_Wt[VOCAB * EMBED];

// ---------------------------------------------------------------------------
// Kernel 1: transpose + downconvert  W[E,V] f32 -> Wt[V,E] f16
// Tile = 128 v x 64 e. Grid = ceil(V/128) = 782, block = 256.
// Read:  float4 (LDG.128), 2048 float4 per tile, 8 per thread -> high MLP.
// Write: each Wt vocab row (128B) stored by one warp as contiguous half2s.
// Last tile handles V%128 with guards.
// ---------------------------------------------------------------------------
__global__ __launch_bounds__(256)
void transpose_W_kernel(const float* __restrict__ W) {
    __shared__ float tile[EMBED][129];         // [e][v], pad keeps banks spread
    const int v0  = blockIdx.x * 128;
    const int tid = threadIdx.x;
    const int vrem = VOCAB - v0;               // >=1

    // Read phase: 64 e-rows x 32 float4 = 2048 float4; 8 per thread.
    #pragma unroll
    for (int r = 0; r < 8; r++) {
        const int idx = tid + r * 256;         // 0..2047
        const int e   = idx >> 5;              // 0..63
        const int c   = idx & 31;              // float4 col 0..31
        const int v   = c * 4;
        if (v + 3 < vrem) {
            const float4 f = __ldg(reinterpret_cast<const float4*>(
                W + (size_t)e * VOCAB + v0) + c);
            tile[e][v]     = f.x;
            tile[e][v + 1] = f.y;
            tile[e][v + 2] = f.z;
            tile[e][v + 3] = f.w;
        } else {
            #pragma unroll
            for (int q = 0; q < 4; q++) {
                if (v + q < vrem)
                    tile[e][v + q] = __ldg(W + (size_t)e * VOCAB + v0 + v + q);
            }
        }
    }
    __syncthreads();

    // Write phase: 128 vrows x 32 half2 = 4096 half2; warp = one 128B vrow.
    __half2* WtH2 = reinterpret_cast<__half2*>(g_Wt);
    #pragma unroll
    for (int r = 0; r < 16; r++) {
        const int idx  = tid + r * 256;
        const int vrow = idx >> 5;             // 0..127 (constant per warp)
        const int c    = idx & 31;             // half2 col
        if (vrow < vrem) {
            const float2 f = make_float2(tile[2 * c][vrow], tile[2 * c + 1][vrow]);
            WtH2[(size_t)(v0 + vrow) * (EMBED / 2) + c] = __float22half2_rn(f);
        }
    }
}

// ---------------------------------------------------------------------------
// Kernel 2: persistent gather-reduce.
// 8 lanes per output row; groups grid-stride over all rows. Steady-state
// streaming (no per-CTA front-batched LDG spike, no syncthreads) to avoid
// cross-CTA L1tex queue spread. fp32 accumulation.
// ---------------------------------------------------------------------------
#define GTHREADS 256
#define GBLOCKS  (148 * 4)

__global__ __launch_bounds__(GTHREADS)
void gather_reduce_kernel(const int* __restrict__ ids,
                          const float* __restrict__ bias,
                          float* __restrict__ out) {
    const int lane   = threadIdx.x & 7;        // owns e in [8*lane, 8*lane+8)
    const int group0 = (blockIdx.x * GTHREADS + threadIdx.x) >> 3;
    const int stride = (GBLOCKS * GTHREADS) >> 3;   // total row-groups

    // Bias: 8 floats per lane, loop-invariant (L1-resident).
    const float4 b0 = __ldg(reinterpret_cast<const float4*>(bias) + 2 * lane);
    const float4 b1 = __ldg(reinterpret_cast<const float4*>(bias) + 2 * lane + 1);

    const float4* WtV = reinterpret_cast<const float4*>(g_Wt);  // 16B chunks

    for (int row = group0; row < BROWS; row += stride) {
        const int* idp = ids + (size_t)row * KIDS;

        int id[KIDS];
        #pragma unroll
        for (int k = 0; k < KIDS; k++) id[k] = __ldg(idp + k);

        float acc[8] = { b0.x, b0.y, b0.z, b0.w, b1.x, b1.y, b1.z, b1.w };

        #pragma unroll
        for (int k = 0; k < KIDS; k++) {
            const float4 raw = __ldg(&WtV[(size_t)id[k] * 8 + lane]);
            const __half2* h = reinterpret_cast<const __half2*>(&raw);
            #pragma unroll
            for (int p = 0; p < 4; p++) {
                const float2 f = __half22float2(h[p]);
                acc[2 * p]     += f.x;
                acc[2 * p + 1] += f.y;
            }
        }

        float4* o = reinterpret_cast<float4*>(out + (size_t)row * EMBED + lane * 8);
        o[0] = make_float4(acc[0], acc[1], acc[2], acc[3]);
        o[1] = make_float4(acc[4], acc[5], acc[6], acc[7]);
    }
}

// ---------------------------------------------------------------------------
// Launch: inputs in metadata order: content_input (int32), W (f32), b (f32)
// ---------------------------------------------------------------------------
extern "C" void kernel_launch(void* const* d_in, const int* in_sizes, int n_in,
                              void* d_out, int out_size) {
    const int*   ids  = (const int*)  d_in[0];   // [B, S, K] int32
    const float* W    = (const float*)d_in[1];   // [E, V] f32
    const float* bias = (const float*)d_in[2];   // [E] f32
    float*       out  = (float*)d_out;           // [B, S, E] f32

    const int tblocks = (VOCAB + 127) / 128;     // 782
    transpose_W_kernel<<<tblocks, 256>>>(W);

    gather_reduce_kernel<<<GBLOCKS, GTHREADS>>>(ids, bias, out);
}

// round 10
// speedup vs baseline: 1.3205x; 1.3205x over previous
#include <cuda_runtime.h>
#include <cuda_fp16.h>
#include <stdint.h>

#define VOCAB 100000
#define EMBED 64
#define KIDS  20
#define BROWS (1024 * 50)          // B*S output rows

// Wt in fp16, [V, E]: each vocab row = 64 halves = 128 B = ONE L2 line.
// 12.8 MB — L2-resident (126 MB L2).
__device__ __half g_Wt[VOCAB * EMBED];

// ---------------------------------------------------------------------------
// Kernel 1: transpose + downconvert  W[E,V] f32 -> Wt[V,E] f16
// Tile = 32 v x 64 e (full embed dim). Grid = V/32 = 3125, block = 256.
// Read:  float4 (LDG.128): 512 float4 per tile, 2 per thread.
// Write: each Wt vocab row (128 B) stored by one warp as contiguous half2s.
// ---------------------------------------------------------------------------
__global__ __launch_bounds__(256)
void transpose_W_kernel(const float* __restrict__ W) {
    __shared__ float tile[EMBED][33];          // [e][v], +1 pad
    const int v0  = blockIdx.x * 32;
    const int tid = threadIdx.x;

    // Read: 64 e-rows x 8 float4 = 512 float4; 2 per thread, coalesced.
    #pragma unroll
    for (int r = 0; r < 2; r++) {
        const int idx = tid + r * 256;         // 0..511
        const int e   = idx >> 3;              // 0..63
        const int c   = idx & 7;               // float4 col 0..7
        const float4 f = __ldg(reinterpret_cast<const float4*>(
            W + (size_t)e * VOCAB + v0) + c);
        tile[e][4 * c]     = f.x;
        tile[e][4 * c + 1] = f.y;
        tile[e][4 * c + 2] = f.z;
        tile[e][4 * c + 3] = f.w;
    }
    __syncthreads();

    // Write: 32 vrows x 32 half2 = 1024 half2; warp = one full 128B vrow.
    __half2* WtH2 = reinterpret_cast<__half2*>(g_Wt);
    #pragma unroll
    for (int r = 0; r < 4; r++) {
        const int idx  = tid + r * 256;
        const int vrow = idx >> 5;             // 0..31 (constant per warp)
        const int c    = idx & 31;             // half2 col 0..31
        const float2 f = make_float2(tile[2 * c][vrow], tile[2 * c + 1][vrow]);
        WtH2[(size_t)(v0 + vrow) * (EMBED / 2) + c] = __float22half2_rn(f);
    }
}

// ---------------------------------------------------------------------------
// Kernel 2: gather-reduce (R4-proven shape). 8 lanes per row (lane owns
// 8 embeds = 16 B of the 128 B row), 32 rows per 256-thread block.
// 20 independent LDG.128 per thread; fp32 accumulation.
// __launch_bounds__(256, 8): cap regs at 32 -> 8 CTAs/SM -> full occupancy.
// ---------------------------------------------------------------------------
#define ROWS_PER_BLOCK 32
#define THREADS 256

__global__ __launch_bounds__(THREADS, 8)
void gather_reduce_kernel(const int* __restrict__ ids,
                          const float* __restrict__ bias,
                          float* __restrict__ out) {
    __shared__ int s_ids[ROWS_PER_BLOCK * KIDS];   // 640 ints

    const int tid = threadIdx.x;
    const size_t block_id_base = (size_t)blockIdx.x * (ROWS_PER_BLOCK * KIDS);

    // Coalesced stage of this block's 640 ids.
    #pragma unroll
    for (int i = tid; i < ROWS_PER_BLOCK * KIDS; i += THREADS) {
        s_ids[i] = __ldg(ids + block_id_base + i);
    }

    const int row_local = tid >> 3;     // 0..31
    const int lane      = tid & 7;      // 0..7, owns e in [8*lane, 8*lane+8)

    // Bias: 8 floats per lane, broadcast across rows (L1-resident).
    const float4 b0 = __ldg(reinterpret_cast<const float4*>(bias) + 2 * lane);
    const float4 b1 = __ldg(reinterpret_cast<const float4*>(bias) + 2 * lane + 1);
    float acc[8] = { b0.x, b0.y, b0.z, b0.w, b1.x, b1.y, b1.z, b1.w };

    __syncthreads();

    int id[KIDS];
    #pragma unroll
    for (int k = 0; k < KIDS; k++) id[k] = s_ids[row_local * KIDS + k];

    const float4* WtV = reinterpret_cast<const float4*>(g_Wt);  // 16B = 8 halves

    #pragma unroll
    for (int k = 0; k < KIDS; k++) {
        const float4 raw = __ldg(&WtV[(size_t)id[k] * 8 + lane]);
        const __half2* h = reinterpret_cast<const __half2*>(&raw);
        #pragma unroll
        for (int p = 0; p < 4; p++) {
            const float2 f = __half22float2(h[p]);
            acc[2 * p]     += f.x;
            acc[2 * p + 1] += f.y;
        }
    }

    // Output: lane writes 32 B; warp's 4 rows = 512 B contiguous.
    const size_t row = (size_t)blockIdx.x * ROWS_PER_BLOCK + row_local;
    float4* o = reinterpret_cast<float4*>(out + row * EMBED + lane * 8);
    o[0] = make_float4(acc[0], acc[1], acc[2], acc[3]);
    o[1] = make_float4(acc[4], acc[5], acc[6], acc[7]);
}

// ---------------------------------------------------------------------------
// Launch: inputs in metadata order: content_input (int32), W (f32), b (f32)
// ---------------------------------------------------------------------------
extern "C" void kernel_launch(void* const* d_in, const int* in_sizes, int n_in,
                              void* d_out, int out_size) {
    const int*   ids  = (const int*)  d_in[0];   // [B, S, K] int32
    const float* W    = (const float*)d_in[1];   // [E, V] f32
    const float* bias = (const float*)d_in[2];   // [E] f32
    float*       out  = (float*)d_out;           // [B, S, E] f32

    transpose_W_kernel<<<VOCAB / 32, 256>>>(W);  // 3125 blocks

    const int blocks = BROWS / ROWS_PER_BLOCK;   // 1600
    gather_reduce_kernel<<<blocks, THREADS>>>(ids, bias, out);
}